// round 9
// baseline (speedup 1.0000x reference)
#include <cuda_runtime.h>
#include <cuda_fp16.h>
#include <cstdint>

#define BATCH 8
#define CCH   128
#define HH    128
#define WW    256
#define KS    9
#define NTOT  (BATCH*CCH*HH*WW)

__device__ float    g_tmp[NTOT];        // transposed layout scratch
// per-(pass,batch) barrier counters, 256B apart (distinct LTS slices)
__device__ unsigned g_ctrs[4][BATCH][64];

__device__ __forceinline__ unsigned ld_acq(const unsigned* p) {
    unsigned v;
    asm volatile("ld.acquire.gpu.global.u32 %0, [%1];" : "=r"(v) : "l"(p) : "memory");
    return v;
}
__device__ __forceinline__ void red_rel_add1(unsigned* p) {
    asm volatile("red.release.gpu.global.add.u32 [%0], 1;" :: "l"(p) : "memory");
}
__device__ __forceinline__ uint32_t smem_u32(const void* p) {
    uint32_t a;
    asm("{ .reg .u64 t; cvta.to.shared.u64 t, %1; cvt.u32.u64 %0, t; }"
        : "=r"(a) : "l"(p));
    return a;
}
__device__ __forceinline__ void ldsm4(uint32_t addr, uint32_t& r0, uint32_t& r1,
                                      uint32_t& r2, uint32_t& r3) {
    asm volatile("ldmatrix.sync.aligned.m8n8.x4.shared.b16 {%0,%1,%2,%3}, [%4];"
                 : "=r"(r0), "=r"(r1), "=r"(r2), "=r"(r3) : "r"(addr));
}
__device__ __forceinline__ void ldsm2(uint32_t addr, uint32_t& r0, uint32_t& r1) {
    asm volatile("ldmatrix.sync.aligned.m8n8.x2.shared.b16 {%0,%1}, [%2];"
                 : "=r"(r0), "=r"(r1) : "r"(addr));
}
__device__ __forceinline__ void mma_f16(float* c, const uint32_t* a,
                                        uint32_t b0, uint32_t b1) {
    asm volatile(
        "mma.sync.aligned.m16n8k16.row.col.f32.f16.f16.f32 "
        "{%0,%1,%2,%3}, {%4,%5,%6,%7}, {%8,%9}, {%0,%1,%2,%3};"
        : "+f"(c[0]), "+f"(c[1]), "+f"(c[2]), "+f"(c[3])
        : "r"(a[0]), "r"(a[1]), "r"(a[2]), "r"(a[3]), "r"(b0), "r"(b1));
}

// ---------------------------------------------------------------------------
// Persistent HMMA pass kernel, fp16, 2-term split on A (carry) only.
// Layout [B, C, S, L]; scan S, conv along L. Block = (l-tile M=64, co-slice
// CO, batch). Occupancy 2 (co-resident blocks hide sync/L2 latency).
// Warp w owns k16-chunk kc=w; iterates term(2) x tap(9) at compile time.
// Each warp holds full 64 x CO accumulators; 8 partials summed via stage.
// out[l,co] = x + relu( sum_{ci,k} w[co,ci,k]*prev[ci,l+k-4] )
// ---------------------------------------------------------------------------
template<int S, int L, int CO>
__global__ void __launch_bounds__(256, 2)
pass_kernel(float* __restrict__ buf, const float* __restrict__ wgt,
            unsigned* __restrict__ ctr_base, int reverse)
{
    constexpr int M    = 64;
    constexpr int ROWS = M + 8;               // 72 (halo 4+4)
    constexpr int AST  = 136;                 // fp16 row stride
    constexpr int MT   = M / 16;              // 4
    constexpr int NT   = CO / 8;              // 2 (V) or 1 (H)
    constexpr int A_SZ = ROWS * AST * 2;      // 19584 B per split
    constexpr int B_SZ = KS * CO * AST * 2;   // weights
    constexpr int SST  = CO + 1;              // stage row stride (floats)

    extern __shared__ char sm[];
    __half* A_p[2] = { (__half*)sm, (__half*)(sm + A_SZ) };
    __half* B_w    = (__half*)(sm + 2*A_SZ);
    float*  stage  = (float*)(sm + 2*A_SZ + B_SZ);   // 8 regions x M x SST
    const uint32_t smb = smem_u32(sm);
    const uint32_t smA[2] = { smb, smb + (uint32_t)A_SZ };
    const uint32_t smB    = smb + 2u*A_SZ;

    const int tid  = threadIdx.x;
    const int wid  = tid >> 5;
    const int lane = tid & 31;
    const int b    = blockIdx.z;
    const int co0  = blockIdx.y * CO;
    const int l0   = blockIdx.x * M;
    const unsigned NB = gridDim.x * gridDim.y;       // blocks per batch
    unsigned* ctr = ctr_base + (size_t)b * 64;

    float* base = buf + (size_t)b * CCH * S * L;

    // ---- resident weights (single fp16): wgt[co][ci][k] -> B[tap][co][ci] ----
    for (int idx = tid; idx < CO * CCH * KS; idx += 256) {
        int co = idx / (CCH * KS);
        int r  = idx % (CCH * KS);
        int ci = r / KS;
        int k  = r % KS;
        float v = wgt[(size_t)(co0 + co) * CCH * KS + (size_t)ci * KS + k];
        B_w[(k * CO + co) * AST + ci] = __float2half_rn(v);
    }
    __syncthreads();

    // ldmatrix lane mapping (x4 tiles: (r0,k0),(r8,k0),(r0,k8),(r8,k8))
    const int lt   = lane >> 3;
    const int lrow = (lane & 7) + ((lt & 1) << 3);
    const int lk   = (lt >> 1) << 3;
    // x2 mapping for CO=8 B tiles: lanes 0-7 (co,k0), 8-15 (co,k8)
    const int l2row = lane & 7;
    const int l2k   = ((lane >> 3) & 1) << 3;

    const int kcb = wid * 16;     // this warp's k16-chunk (ci offset)

    for (int i = 1; i < S; ++i) {
        const int s_cur  = reverse ? (S - 1 - i) : i;
        const int s_prev = reverse ? (s_cur + 1) : (s_cur - 1);

        // ---- A build: carry row -> fp16 hi/lo [l'][ci] ----
        {
            const float* src = base + (size_t)s_prev * L;
#pragma unroll 6
            for (int idx = tid; idx < CCH * ROWS; idx += 256) {
                int ci = idx / ROWS;
                int r  = idx % ROWS;
                int gl = l0 - 4 + r;
                float v = (gl >= 0 && gl < L) ? src[(size_t)ci * S * L + gl] : 0.0f;
                __half hi = __float2half_rn(v);
                __half lo = __float2half_rn(v - __half2float(hi));
                A_p[0][r * AST + ci] = hi;
                A_p[1][r * AST + ci] = lo;
            }
        }
        __syncthreads();

        // ---- HMMA: term(2) x tap(9) unrolled, kc = wid ----
        float acc[MT][NT][4];
#pragma unroll
        for (int mt = 0; mt < MT; ++mt)
#pragma unroll
            for (int nt = 0; nt < NT; ++nt)
#pragma unroll
                for (int e = 0; e < 4; ++e) acc[mt][nt][e] = 0.0f;

#pragma unroll
        for (int term = 0; term < 2; ++term) {
            const uint32_t aB = smA[term];
#pragma unroll
            for (int tap = 0; tap < KS; ++tap) {
                uint32_t bb[4];
                if constexpr (NT == 2) {
                    uint32_t addr = smB +
                        (uint32_t)(((tap * CO + lrow) * AST + kcb + lk) * 2);
                    ldsm4(addr, bb[0], bb[1], bb[2], bb[3]);
                } else {
                    uint32_t addr = smB +
                        (uint32_t)(((tap * CO + l2row) * AST + kcb + l2k) * 2);
                    ldsm2(addr, bb[0], bb[1]);
                }
#pragma unroll
                for (int mt = 0; mt < MT; ++mt) {
                    uint32_t a[4];
                    uint32_t addr = aB +
                        (uint32_t)(((mt * 16 + tap + lrow) * AST + kcb + lk) * 2);
                    ldsm4(addr, a[0], a[1], a[2], a[3]);
                    if constexpr (NT == 2) {
                        mma_f16(acc[mt][0], a, bb[0], bb[2]);
                        mma_f16(acc[mt][1], a, bb[1], bb[3]);
                    } else {
                        mma_f16(acc[mt][0], a, bb[0], bb[1]);
                    }
                }
            }
        }

        // ---- each warp writes its region; epilogue sums 8 regions ----
        const int row0 = lane >> 2;
        const int colb = (lane & 3) * 2;
#pragma unroll
        for (int mt = 0; mt < MT; ++mt)
#pragma unroll
            for (int nt = 0; nt < NT; ++nt) {
                float* p = stage + (size_t)(wid * M + mt * 16 + row0) * SST
                                 + nt * 8 + colb;
                p[0] = acc[mt][nt][0];  p[1] = acc[mt][nt][1];
                p[8*SST] = acc[mt][nt][2];  p[8*SST + 1] = acc[mt][nt][3];
            }
        __syncthreads();

        // ---- epilogue: out = x + relu( sum of 8 regions ) ----
        {
            const int m = tid & 63;
            const int g = tid >> 6;              // 4 groups
            constexpr int CPT = CO / 4;
#pragma unroll
            for (int c = 0; c < CPT; ++c) {
                const int co = g * CPT + c;
                float v = 0.0f;
#pragma unroll
                for (int r = 0; r < 8; ++r)
                    v += stage[(size_t)(r * M + m) * SST + co];
                float* p = base + ((size_t)(co0 + co) * S + s_cur) * L + l0 + m;
                *p = *p + fmaxf(v, 0.0f);
            }
        }

        // ---- per-batch grid barrier (release/acquire) ----
        __syncthreads();
        if (i < S - 1) {
            if (tid == 0) {
                red_rel_add1(ctr);
                const unsigned tgt = (unsigned)i * NB;
                while (ld_acq(ctr) < tgt) __nanosleep(16);
            }
            __syncthreads();
        }
    }
}

// ---------------------------------------------------------------------------
// Transpose [P, A, B] -> [P, B, A]
// ---------------------------------------------------------------------------
__global__ void transpose_kernel(const float* __restrict__ in,
                                 float* __restrict__ out, int A, int B)
{
    __shared__ float tile[32][33];
    const size_t p = blockIdx.z;
    const int b0 = blockIdx.x * 32;
    const int a0 = blockIdx.y * 32;
    const int tx = threadIdx.x, ty = threadIdx.y;
    const float* ip = in  + p * (size_t)A * B;
    float*       op = out + p * (size_t)A * B;
#pragma unroll
    for (int i = ty; i < 32; i += 8)
        tile[i][tx] = ip[(size_t)(a0+i)*B + (b0+tx)];
    __syncthreads();
#pragma unroll
    for (int i = ty; i < 32; i += 8)
        op[(size_t)(b0+i)*A + (a0+tx)] = tile[tx][i];
}

// Vertical: [B,C,S=H=128,L=W=256], CO=16. Horizontal (transposed): CO=8.
#define PASSV pass_kernel<128,256,16>
#define PASSH pass_kernel<256,128,8>

static constexpr int SMEM_V = 2*19584 + KS*16*136*2 + 8*64*17*4;  // 113152
static constexpr int SMEM_H = 2*19584 + KS* 8*136*2 + 8*64* 9*4;  // 77184

extern "C" void kernel_launch(void* const* d_in, const int* in_sizes, int n_in,
                              void* d_out, int out_size)
{
    const float* x    = (const float*)d_in[0];
    const float* w_ud = (const float*)d_in[1];
    const float* w_du = (const float*)d_in[2];
    const float* w_lr = (const float*)d_in[3];
    const float* w_rl = (const float*)d_in[4];
    float* buf = (float*)d_out;

    float* tbuf = nullptr;
    cudaGetSymbolAddress((void**)&tbuf, g_tmp);
    unsigned* ctr = nullptr;
    cudaGetSymbolAddress((void**)&ctr, g_ctrs);

    cudaFuncSetAttribute(PASSV, cudaFuncAttributeMaxDynamicSharedMemorySize, SMEM_V);
    cudaFuncSetAttribute(PASSH, cudaFuncAttributeMaxDynamicSharedMemorySize, SMEM_H);

    cudaMemsetAsync(ctr, 0, 4*BATCH*64*sizeof(unsigned), 0);
    cudaMemcpyAsync(buf, x, (size_t)NTOT * sizeof(float),
                    cudaMemcpyDeviceToDevice, 0);

    const unsigned PSTRIDE = BATCH * 64;

    // V: 4 l-tiles x 8 co-slices x 8 batches = 256 blocks (<=296 resident @occ2)
    dim3 gv(WW/64, CCH/16, BATCH);
    PASSV<<<gv, 256, SMEM_V>>>(buf, w_ud, ctr + 0*PSTRIDE, 0);
    PASSV<<<gv, 256, SMEM_V>>>(buf, w_du, ctr + 1*PSTRIDE, 1);

    transpose_kernel<<<dim3(WW/32, HH/32, BATCH*CCH), dim3(32,8)>>>(buf, tbuf, HH, WW);

    // H: 2 l-tiles x 16 co-slices x 8 batches = 256 blocks
    dim3 gh(HH/64, CCH/8, BATCH);
    PASSH<<<gh, 256, SMEM_H>>>(tbuf, w_lr, ctr + 2*PSTRIDE, 0);
    PASSH<<<gh, 256, SMEM_H>>>(tbuf, w_rl, ctr + 3*PSTRIDE, 1);

    transpose_kernel<<<dim3(HH/32, WW/32, BATCH*CCH), dim3(32,8)>>>(tbuf, buf, WW, HH);
}

// round 10
// speedup vs baseline: 1.2534x; 1.2534x over previous
#include <cuda_runtime.h>
#include <cuda_fp16.h>
#include <cstdint>

#define BATCH 8
#define CCH   128
#define HH    128
#define WW    256
#define KS    9
#define NTOT  (BATCH*CCH*HH*WW)

__device__ float  g_tmp[NTOT];                       // transposed scratch
// exchange buffers: [b][parity][l_pad][split(2)][ci(128)] fp16, pads stay zero
__device__ __half g_exV[BATCH][2][WW+8][2][CCH];     // V pass: L=256
__device__ __half g_exH[BATCH][2][HH+8][2][CCH];     // H pass: L=128
// per-(pass,b,tile,half) step flags, padded 32B
__device__ unsigned g_flags2[4][BATCH][8][2][8];

__device__ __forceinline__ unsigned ld_acq(const unsigned* p) {
    unsigned v;
    asm volatile("ld.acquire.gpu.global.u32 %0, [%1];" : "=r"(v) : "l"(p) : "memory");
    return v;
}
__device__ __forceinline__ void st_rel(unsigned* p, unsigned v) {
    asm volatile("st.release.gpu.global.u32 [%0], %1;" :: "l"(p), "r"(v) : "memory");
}
__device__ __forceinline__ uint32_t smem_u32(const void* p) {
    uint32_t a;
    asm("{ .reg .u64 t; cvta.to.shared.u64 t, %1; cvt.u32.u64 %0, t; }"
        : "=r"(a) : "l"(p));
    return a;
}
__device__ __forceinline__ void cp16(uint32_t d, const void* s) {
    asm volatile("cp.async.cg.shared.global [%0], [%1], 16;" :: "r"(d), "l"(s));
}
__device__ __forceinline__ void ldsm4(uint32_t addr, uint32_t& r0, uint32_t& r1,
                                      uint32_t& r2, uint32_t& r3) {
    asm volatile("ldmatrix.sync.aligned.m8n8.x4.shared.b16 {%0,%1,%2,%3}, [%4];"
                 : "=r"(r0), "=r"(r1), "=r"(r2), "=r"(r3) : "r"(addr));
}
__device__ __forceinline__ void ldsm2(uint32_t addr, uint32_t& r0, uint32_t& r1) {
    asm volatile("ldmatrix.sync.aligned.m8n8.x2.shared.b16 {%0,%1}, [%2];"
                 : "=r"(r0), "=r"(r1) : "r"(addr));
}
__device__ __forceinline__ void mma_f16(float* c, const uint32_t* a,
                                        uint32_t b0, uint32_t b1) {
    asm volatile(
        "mma.sync.aligned.m16n8k16.row.col.f32.f16.f16.f32 "
        "{%0,%1,%2,%3}, {%4,%5,%6,%7}, {%8,%9}, {%0,%1,%2,%3};"
        : "+f"(c[0]), "+f"(c[1]), "+f"(c[2]), "+f"(c[3])
        : "r"(a[0]), "r"(a[1]), "r"(a[2]), "r"(a[3]), "r"(b0), "r"(b1));
}

// ---------------------------------------------------------------------------
// Neighbor-flag persistent pass kernel. Block = (batch, l-tile M, co-half 64).
// Carry rows flow through a parity-double-buffered fp16 hi/lo exchange buffer
// (A-format); sync = 5 producer flags (co-sibling + 2 l-neighbors x 2 halves),
// NOT a grid barrier. Weights (64 co) resident in smem. Warp owns 8 co.
// out[l,co] = x + relu( sum_{ci,k} w[co,ci,k]*prev[ci,l+k-4] )
// ---------------------------------------------------------------------------
template<int S, int L, int M>
__global__ void __launch_bounds__(256)
pass_kernel(float* __restrict__ buf, const float* __restrict__ wgt,
            unsigned* __restrict__ flags, __half* __restrict__ ex, int reverse)
{
    constexpr int ROWS = M + 8;
    constexpr int AST  = 136;               // A row stride (halfs), 272B
    constexpr int MT   = M / 16;
    constexpr int XST  = M + 4;             // x stage row stride (floats)
    constexpr int NTILE = L / M;            // l-tiles (=8 for both passes)
    // smem offsets (bytes)
    constexpr int SM_A0 = 0;
    constexpr int SM_A1 = ROWS * AST * 2;
    constexpr int SM_W  = 2 * SM_A1;
    constexpr int SM_X  = SM_W + KS * 64 * AST * 2;

    extern __shared__ char sm[];
    const uint32_t smb = smem_u32(sm);
    const uint32_t smA[2] = { smb + SM_A0, smb + SM_A1 };
    const uint32_t smW    = smb + SM_W;
    float* xs = (float*)(sm + SM_X);

    const int tid  = threadIdx.x;
    const int wid  = tid >> 5;
    const int lane = tid & 31;
    const int tile = blockIdx.x;
    const int half = blockIdx.y;
    const int b    = blockIdx.z;
    const int l0   = tile * M;
    const int co0h = half * 64;

    float* base = buf + (size_t)b * CCH * S * L;
    __half* exb[2] = { ex + ((size_t)b * 2 + 0) * (L + 8) * 256,
                       ex + ((size_t)b * 2 + 1) * (L + 8) * 256 };

    // flag pointers
    unsigned* fown = flags + (((b * NTILE + tile) * 2 + half) * 8);
    unsigned* pollf[5];
    pollf[0] = flags + (((b * NTILE + tile) * 2 + (1 - half)) * 8);
    pollf[1] = (tile > 0)       ? flags + (((b * NTILE + tile - 1) * 2 + 0) * 8) : nullptr;
    pollf[2] = (tile > 0)       ? flags + (((b * NTILE + tile - 1) * 2 + 1) * 8) : nullptr;
    pollf[3] = (tile < NTILE-1) ? flags + (((b * NTILE + tile + 1) * 2 + 0) * 8) : nullptr;
    pollf[4] = (tile < NTILE-1) ? flags + (((b * NTILE + tile + 1) * 2 + 1) * 8) : nullptr;

    // ---- resident weights: wgt[co][ci][k] -> W[tap*64+co][ci] fp16 ----
    {
        __half* W = (__half*)(sm + SM_W);
        for (int idx = tid; idx < 64 * CCH * KS; idx += 256) {
            int co = idx / (CCH * KS);
            int r  = idx % (CCH * KS);
            int ci = r / KS;
            int k  = r % KS;
            float v = wgt[(size_t)(co0h + co) * CCH * KS + (size_t)ci * KS + k];
            W[(k * 64 + co) * AST + ci] = __float2half_rn(v);
        }
    }

    // ---- initial: logical step 0 = row s0 of x (unchanged), write ex par0 ----
    {
        const int s0 = reverse ? (S - 1) : 0;
        const float* src = base + (size_t)s0 * L;
        for (int idx = tid; idx < M * 64; idx += 256) {
            int l  = idx % M;
            int co = idx / M;
            float v = src[(size_t)(co0h + co) * S * L + l0 + l];
            __half hi = __float2half_rn(v);
            __half lo = __float2half_rn(v - __half2float(hi));
            size_t pos = (size_t)(l0 + l + 4) * 256 + (co0h + co);
            exb[0][pos]       = hi;
            exb[0][pos + 128] = lo;
        }
    }
    __syncthreads();
    if (tid == 0) st_rel(fown, 1u);

    // ldmatrix lane mappings
    const int lt    = lane >> 3;
    const int lrow  = (lane & 7) + ((lt & 1) << 3);
    const int lk    = (lt >> 1) << 3;
    const int l2row = lane & 7;
    const int l2k   = ((lane >> 3) & 1) << 3;
    const int r4    = lane >> 2;
    const int cp2   = (lane & 3) * 2;
    const int coL   = wid * 8 + cp2;

    for (int i = 1; i < S; ++i) {
        const int s_cur = reverse ? (S - 1 - i) : i;
        const int pprev = (i - 1) & 1;
        const int pcur  = i & 1;

        // ---- wait producers (5 flags >= i) ----
        if (tid < 5) {
            unsigned* f = pollf[tid];
            if (f) while (ld_acq(f) < (unsigned)i) __nanosleep(16);
        }
        __syncthreads();

        // ---- cp.async: ex window -> A smem; x row -> x stage ----
        {
            const __half* src = exb[pprev] + (size_t)l0 * 256;
#pragma unroll
            for (int t = 0; t < (ROWS * 32) / 256; ++t) {
                int idx = tid + t * 256;
                int row = idx >> 5;
                int c   = idx & 31;                 // split*16 + chunk
                uint32_t dst = smA[c >> 4] + row * (AST*2) + (c & 15) * 16;
                cp16(dst, src + (size_t)row * 256 + (c & 15) * 8 + ((c >> 4) << 7));
            }
            const float* xsrc = base + (size_t)s_cur * L + l0;
#pragma unroll
            for (int t = 0; t < (64 * (M/4)) / 256; ++t) {
                int idx = tid + t * 256;
                int co  = idx / (M / 4);
                int lq  = idx % (M / 4);
                uint32_t dst = smb + SM_X + (co * XST + lq * 4) * 4;
                cp16(dst, xsrc + (size_t)(co0h + co) * S * L + lq * 4);
            }
            asm volatile("cp.async.commit_group;" ::: "memory");
            asm volatile("cp.async.wait_group 0;" ::: "memory");
        }
        __syncthreads();

        // ---- HMMA: warp owns 8 co; loop tap x kc x term x mt ----
        float acc[MT][4];
#pragma unroll
        for (int mt = 0; mt < MT; ++mt)
#pragma unroll
            for (int e = 0; e < 4; ++e) acc[mt][e] = 0.0f;

#pragma unroll
        for (int tap = 0; tap < KS; ++tap) {
#pragma unroll
            for (int kc = 0; kc < 8; ++kc) {
                uint32_t b0, b1;
                ldsm2(smW + (uint32_t)(((tap * 64 + wid * 8 + l2row) * AST
                                        + kc * 16 + l2k) * 2), b0, b1);
#pragma unroll
                for (int term = 0; term < 2; ++term) {
#pragma unroll
                    for (int mt = 0; mt < MT; ++mt) {
                        uint32_t a[4];
                        ldsm4(smA[term] + (uint32_t)(((mt * 16 + tap + lrow) * AST
                                                      + kc * 16 + lk) * 2),
                              a[0], a[1], a[2], a[3]);
                        mma_f16(acc[mt], a, b0, b1);
                    }
                }
            }
        }

        // ---- epilogue: out = x + relu(acc); STG buf + STG ex(par cur) ----
        {
            __half* exc = exb[pcur];
#pragma unroll
            for (int mt = 0; mt < MT; ++mt) {
#pragma unroll
                for (int h2 = 0; h2 < 2; ++h2) {
                    const int ll = mt * 16 + r4 + h2 * 8;
                    float x0 = xs[coL * XST + ll];
                    float x1 = xs[(coL + 1) * XST + ll];
                    float o0 = x0 + fmaxf(acc[mt][h2 * 2 + 0], 0.0f);
                    float o1 = x1 + fmaxf(acc[mt][h2 * 2 + 1], 0.0f);
                    base[(size_t)(co0h + coL)     * S * L + (size_t)s_cur * L + l0 + ll] = o0;
                    base[(size_t)(co0h + coL + 1) * S * L + (size_t)s_cur * L + l0 + ll] = o1;
                    __half h0 = __float2half_rn(o0);
                    __half h1 = __float2half_rn(o1);
                    __half g0 = __float2half_rn(o0 - __half2float(h0));
                    __half g1 = __float2half_rn(o1 - __half2float(h1));
                    size_t pos = (size_t)(l0 + ll + 4) * 256 + (co0h + coL);
                    *(__half2*)(exc + pos)       = __halves2half2(h0, h1);
                    *(__half2*)(exc + pos + 128) = __halves2half2(g0, g1);
                }
            }
        }

        __syncthreads();
        if (tid == 0) st_rel(fown, (unsigned)(i + 1));
    }
}

// ---------------------------------------------------------------------------
// Transpose [P, A, B] -> [P, B, A]
// ---------------------------------------------------------------------------
__global__ void transpose_kernel(const float* __restrict__ in,
                                 float* __restrict__ out, int A, int B)
{
    __shared__ float tile[32][33];
    const size_t p = blockIdx.z;
    const int b0 = blockIdx.x * 32;
    const int a0 = blockIdx.y * 32;
    const int tx = threadIdx.x, ty = threadIdx.y;
    const float* ip = in  + p * (size_t)A * B;
    float*       op = out + p * (size_t)A * B;
#pragma unroll
    for (int i = ty; i < 32; i += 8)
        tile[i][tx] = ip[(size_t)(a0+i)*B + (b0+tx)];
    __syncthreads();
#pragma unroll
    for (int i = ty; i < 32; i += 8)
        op[(size_t)(b0+i)*A + (a0+tx)] = tile[tx][i];
}

// Vertical: [B,C,S=H=128,L=W=256], M=32. Horizontal (transposed): S=256,L=128, M=16.
#define PASSV pass_kernel<128,256,32>
#define PASSH pass_kernel<256,128,16>

static constexpr int SMEM_V = 2*(40*136*2) + KS*64*136*2 + 64*36*4;  // 187648
static constexpr int SMEM_H = 2*(24*136*2) + KS*64*136*2 + 64*20*4;  // 174848

extern "C" void kernel_launch(void* const* d_in, const int* in_sizes, int n_in,
                              void* d_out, int out_size)
{
    const float* x    = (const float*)d_in[0];
    const float* w_ud = (const float*)d_in[1];
    const float* w_du = (const float*)d_in[2];
    const float* w_lr = (const float*)d_in[3];
    const float* w_rl = (const float*)d_in[4];
    float* buf = (float*)d_out;

    float* tbuf = nullptr;
    cudaGetSymbolAddress((void**)&tbuf, g_tmp);
    unsigned* flags = nullptr;
    cudaGetSymbolAddress((void**)&flags, g_flags2);
    __half* exV = nullptr;
    cudaGetSymbolAddress((void**)&exV, g_exV);
    __half* exH = nullptr;
    cudaGetSymbolAddress((void**)&exH, g_exH);

    cudaFuncSetAttribute(PASSV, cudaFuncAttributeMaxDynamicSharedMemorySize, SMEM_V);
    cudaFuncSetAttribute(PASSH, cudaFuncAttributeMaxDynamicSharedMemorySize, SMEM_H);

    // reset step flags (exchange-buffer pads are never written and stay zero)
    cudaMemsetAsync(flags, 0, 4 * BATCH * 8 * 2 * 8 * sizeof(unsigned), 0);
    cudaMemcpyAsync(buf, x, (size_t)NTOT * sizeof(float),
                    cudaMemcpyDeviceToDevice, 0);

    const unsigned PSTRIDE = BATCH * 8 * 2 * 8;   // flags per pass

    dim3 g(8, 2, BATCH);   // 128 blocks, occ1, all resident
    PASSV<<<g, 256, SMEM_V>>>(buf, w_ud, flags + 0*PSTRIDE, exV, 0);
    PASSV<<<g, 256, SMEM_V>>>(buf, w_du, flags + 1*PSTRIDE, exV, 1);

    transpose_kernel<<<dim3(WW/32, HH/32, BATCH*CCH), dim3(32,8)>>>(buf, tbuf, HH, WW);

    PASSH<<<g, 256, SMEM_H>>>(tbuf, w_lr, flags + 2*PSTRIDE, exH, 0);
    PASSH<<<g, 256, SMEM_H>>>(tbuf, w_rl, flags + 3*PSTRIDE, exH, 1);

    transpose_kernel<<<dim3(HH/32, WW/32, BATCH*CCH), dim3(32,8)>>>(tbuf, buf, WW, HH);
}

// round 11
// speedup vs baseline: 1.4302x; 1.1410x over previous
#include <cuda_runtime.h>
#include <cuda_fp16.h>
#include <cstdint>

#define BATCH 8
#define CCH   128
#define HH    128
#define WW    256
#define KS    9
#define NTOT  (BATCH*CCH*HH*WW)

__device__ float g_tmp[NTOT];                        // transposed scratch
// halo buffers: [b][tile][side][parity][split][4 rows][128 ci] fp16
__device__ __align__(16) __half g_halo[BATCH][8][2][2][2][4][128];
// per-(pass,b,tile,half) step flags, padded 32B
__device__ unsigned g_flags[4][BATCH][8][2][8];

__device__ __forceinline__ unsigned ld_acq(const unsigned* p) {
    unsigned v;
    asm volatile("ld.acquire.gpu.global.u32 %0, [%1];" : "=r"(v) : "l"(p) : "memory");
    return v;
}
__device__ __forceinline__ void st_rel(unsigned* p, unsigned v) {
    asm volatile("st.release.gpu.global.u32 [%0], %1;" :: "l"(p), "r"(v) : "memory");
}
__device__ __forceinline__ uint32_t smem_u32(const void* p) {
    uint32_t a;
    asm("{ .reg .u64 t; cvta.to.shared.u64 t, %1; cvt.u32.u64 %0, t; }"
        : "=r"(a) : "l"(p));
    return a;
}
__device__ __forceinline__ uint32_t mapa_peer(uint32_t addr, uint32_t rank) {
    uint32_t r;
    asm("mapa.shared::cluster.u32 %0, %1, %2;" : "=r"(r) : "r"(addr), "r"(rank));
    return r;
}
__device__ __forceinline__ void st_dsmem(uint32_t addr, uint32_t v) {
    asm volatile("st.shared::cluster.u32 [%0], %1;" :: "r"(addr), "r"(v) : "memory");
}
__device__ __forceinline__ void sts32(uint32_t addr, uint32_t v) {
    asm volatile("st.shared.u32 [%0], %1;" :: "r"(addr), "r"(v) : "memory");
}
__device__ __forceinline__ void cluster_sync() {
    asm volatile("barrier.cluster.arrive.aligned;" ::: "memory");
    asm volatile("barrier.cluster.wait.aligned;" ::: "memory");
}
__device__ __forceinline__ uint32_t ctarank() {
    uint32_t r; asm("mov.u32 %0, %%cluster_ctarank;" : "=r"(r)); return r;
}
__device__ __forceinline__ void cp16(uint32_t d, const void* s) {
    asm volatile("cp.async.cg.shared.global [%0], [%1], 16;" :: "r"(d), "l"(s));
}
__device__ __forceinline__ void ldsm4(uint32_t addr, uint32_t& r0, uint32_t& r1,
                                      uint32_t& r2, uint32_t& r3) {
    asm volatile("ldmatrix.sync.aligned.m8n8.x4.shared.b16 {%0,%1,%2,%3}, [%4];"
                 : "=r"(r0), "=r"(r1), "=r"(r2), "=r"(r3) : "r"(addr));
}
__device__ __forceinline__ void ldsm2(uint32_t addr, uint32_t& r0, uint32_t& r1) {
    asm volatile("ldmatrix.sync.aligned.m8n8.x2.shared.b16 {%0,%1}, [%2];"
                 : "=r"(r0), "=r"(r1) : "r"(addr));
}
__device__ __forceinline__ void mma_f16(float* c, const uint32_t* a,
                                        uint32_t b0, uint32_t b1) {
    asm volatile(
        "mma.sync.aligned.m16n8k16.row.col.f32.f16.f16.f32 "
        "{%0,%1,%2,%3}, {%4,%5,%6,%7}, {%8,%9}, {%0,%1,%2,%3};"
        : "+f"(c[0]), "+f"(c[1]), "+f"(c[2]), "+f"(c[3])
        : "r"(a[0]), "r"(a[1]), "r"(a[2]), "r"(a[3]), "r"(b0), "r"(b1));
}
__device__ __forceinline__ uint32_t h2u(__half a, __half b) {
    __half2 t = __halves2half2(a, b);
    return *reinterpret_cast<uint32_t*>(&t);
}

// ---------------------------------------------------------------------------
// Cluster(2) persistent pass kernel. CTA = (co-half 64, l-tile M, batch);
// the two co-halves of a tile form a cluster. Carry stays in smem:
//  - own 64 ci: epilogue writes directly into parity-buffered A tile
//  - sibling 64 ci: epilogue writes into sibling's A tile via DSMEM,
//    visibility via one cluster.sync per step
//  - +-4 column l-halos: global halo buffers + R9 flag protocol (parity-
//    double-buffered; producer t step-i overwrite of parity i&1 is safe
//    because t polls its neighbors >= i-1 first, which happens-after they
//    consumed the step i-2 slot)
// fp16 weights, 2-term fp16 split on carry (A). Warp owns NT*8 co x 16 l.
// out[l,co] = x + relu( sum_{ci,k} w[co,ci,k]*prev[ci,l+k-4] )
// ---------------------------------------------------------------------------
template<int S, int L, int M>
__global__ void __cluster_dims__(2, 1, 1) __launch_bounds__(256, 1)
pass_kernel(float* __restrict__ buf, const float* __restrict__ wgt,
            unsigned* __restrict__ flags, int reverse)
{
    constexpr int ROWS   = M + 8;
    constexpr int AST    = 136;                  // A/W row stride (halfs)
    constexpr int ASPLIT = ROWS * AST * 2;       // bytes per (parity,split)
    constexpr int SM_W   = 4 * ASPLIT;
    constexpr int W_SZ   = KS * 64 * AST * 2;
    constexpr int SM_X   = SM_W + W_SZ;
    constexpr int XST    = M + 4;                // x stage row stride (floats)
    constexpr int NT     = M / 16;               // n8-tiles per warp (2 V, 1 H)
    constexpr int COW    = NT * 8;               // co per warp

    extern __shared__ char sm[];
    const uint32_t smb = smem_u32(sm);
    float* xs = (float*)(sm + SM_X);

    const int tid  = threadIdx.x;
    const int wid  = tid >> 5;
    const int lane = tid & 31;
    const int half = blockIdx.x;                 // cluster rank
    const int tile = blockIdx.y;
    const int b    = blockIdx.z;
    const int l0   = tile * M;
    const int co0h = half * 64;
    const uint32_t peer = 1u - ctarank();
    const uint32_t rbase = mapa_peer(smb, peer);

    float* base = buf + (size_t)b * CCH * S * L;
    unsigned* fown = flags + (((b * 8 + tile) * 2 + half) * 8);
    unsigned* pollf[4];
    pollf[0] = (tile > 0) ? flags + (((b * 8 + tile - 1) * 2 + 0) * 8) : nullptr;
    pollf[1] = (tile > 0) ? flags + (((b * 8 + tile - 1) * 2 + 1) * 8) : nullptr;
    pollf[2] = (tile < 7) ? flags + (((b * 8 + tile + 1) * 2 + 0) * 8) : nullptr;
    pollf[3] = (tile < 7) ? flags + (((b * 8 + tile + 1) * 2 + 1) * 8) : nullptr;

    // ---- resident weights: wgt[co][ci][k] -> W[tap*64+co_local][ci] fp16 ----
    {
        __half* W = (__half*)(sm + SM_W);
        for (int idx = tid; idx < 64 * CCH * KS; idx += 256) {
            int co = idx / (CCH * KS);
            int r  = idx % (CCH * KS);
            int ci = r / KS;
            int k  = r % KS;
            float v = wgt[(size_t)(co0h + co) * CCH * KS + (size_t)ci * KS + k];
            W[(k * 64 + co) * AST + ci] = __float2half_rn(v);
        }
    }
    // ---- zero A (both parities), then fill A[par0] with x row s0 window ----
    for (int idx = tid; idx < 4 * ASPLIT / 4; idx += 256)
        ((uint32_t*)sm)[idx] = 0u;
    __syncthreads();
    {
        const int s0 = reverse ? (S - 1) : 0;
        const float* src = base + (size_t)s0 * L;
        __half* A_hi = (__half*)sm;              // parity0, split hi
        __half* A_lo = (__half*)(sm + ASPLIT);   // parity0, split lo
        for (int idx = tid; idx < CCH * ROWS; idx += 256) {
            int ci = idx / ROWS;
            int r  = idx % ROWS;
            int gl = l0 - 4 + r;
            float v = (gl >= 0 && gl < L) ? src[(size_t)ci * S * L + gl] : 0.0f;
            __half hi = __float2half_rn(v);
            __half lo = __float2half_rn(v - __half2float(hi));
            A_hi[r * AST + ci] = hi;
            A_lo[r * AST + ci] = lo;
        }
    }
    __syncthreads();

    // warp tiling: V (NT=2): g=wid>>1 (co16), mt=wid&1. H (NT=1): g=wid, mt=0.
    const int g  = (NT == 2) ? (wid >> 1) : wid;
    const int mt = (NT == 2) ? (wid & 1) : 0;
    const int lt    = lane >> 3;
    const int lrow  = (lane & 7) + ((lt & 1) << 3);
    const int lk    = (lt >> 1) << 3;
    const int l2row = lane & 7;
    const int l2k   = ((lane >> 3) & 1) << 3;
    const int r4    = lane >> 2;
    const int cp2   = (lane & 3) * 2;
    const uint32_t smW = smb + SM_W;

    for (int i = 1; i < S; ++i) {
        const int s_cur = reverse ? (S - 1 - i) : i;
        const int pprev = (i - 1) & 1;
        const int pcur  = i & 1;

        // ---- x row prefetch (independent of neighbors) ----
        {
            const float* xsrc = base + (size_t)s_cur * L + l0;
#pragma unroll
            for (int t = 0; t < (64 * (M / 4)) / 256; ++t) {
                int idx = tid + t * 256;
                int co  = idx / (M / 4);
                int lq  = idx % (M / 4);
                cp16(smb + SM_X + (uint32_t)(co * XST + lq * 4) * 4,
                     xsrc + (size_t)(co0h + co) * S * L + lq * 4);
            }
        }
        // ---- wait l-neighbors (step >= 2), then pull 4-col halos ----
        if (i >= 2) {
            if (tid < 4) {
                unsigned* f = pollf[tid];
                if (f) while (ld_acq(f) < (unsigned)(i - 1)) __nanosleep(16);
            }
            __syncthreads();
            const int s     = tid >> 7;            // 0 = left, 1 = right
            const int split = (tid >> 6) & 1;
            const int r     = (tid >> 4) & 3;
            const int c     = tid & 15;
            const bool have = (s == 0) ? (tile > 0) : (tile < 7);
            if (have) {
                const __half* src = &g_halo[b][s == 0 ? tile - 1 : tile + 1]
                                           [s == 0 ? 1 : 0][pprev][split][r][c * 8];
                uint32_t dst = smb + (uint32_t)(pprev * 2 + split) * ASPLIT
                             + (uint32_t)(((s == 0 ? r : M + 4 + r) * AST + c * 8) * 2);
                cp16(dst, src);
            }
        }
        asm volatile("cp.async.commit_group;" ::: "memory");
        asm volatile("cp.async.wait_group 0;" ::: "memory");
        __syncthreads();

        // ---- HMMA from A[pprev] ----
        float acc[NT][4];
#pragma unroll
        for (int nt = 0; nt < NT; ++nt)
#pragma unroll
            for (int e = 0; e < 4; ++e) acc[nt][e] = 0.0f;

        const uint32_t aB0 = smb + (uint32_t)(pprev * 2 + 0) * ASPLIT;
        const uint32_t aB1 = smb + (uint32_t)(pprev * 2 + 1) * ASPLIT;
#pragma unroll
        for (int tap = 0; tap < KS; ++tap) {
#pragma unroll
            for (int kc = 0; kc < 8; ++kc) {
                uint32_t b0, b1, b2, b3;
                if constexpr (NT == 2) {
                    ldsm4(smW + (uint32_t)(((tap * 64 + g * 16 + lrow) * AST
                                            + kc * 16 + lk) * 2), b0, b1, b2, b3);
                } else {
                    ldsm2(smW + (uint32_t)(((tap * 64 + g * 8 + l2row) * AST
                                            + kc * 16 + l2k) * 2), b0, b1);
                }
                const uint32_t arow = (uint32_t)(((mt * 16 + tap + lrow) * AST
                                                  + kc * 16 + lk) * 2);
                uint32_t a[4];
                ldsm4(aB0 + arow, a[0], a[1], a[2], a[3]);
                if constexpr (NT == 2) {
                    mma_f16(acc[0], a, b0, b2);
                    mma_f16(acc[1], a, b1, b3);
                } else {
                    mma_f16(acc[0], a, b0, b1);
                }
                ldsm4(aB1 + arow, a[0], a[1], a[2], a[3]);
                if constexpr (NT == 2) {
                    mma_f16(acc[0], a, b0, b2);
                    mma_f16(acc[1], a, b1, b3);
                } else {
                    mma_f16(acc[0], a, b0, b1);
                }
            }
        }

        // ---- epilogue: o = x + relu(acc); write buf, own A, sibling A, halo ----
        {
            const uint32_t oHi = (uint32_t)(pcur * 2 + 0) * ASPLIT;
            const uint32_t oLo = (uint32_t)(pcur * 2 + 1) * ASPLIT;
#pragma unroll
            for (int nt = 0; nt < NT; ++nt) {
#pragma unroll
                for (int h2 = 0; h2 < 2; ++h2) {
                    const int ll = mt * 16 + r4 + h2 * 8;
                    const int co = g * COW + nt * 8 + cp2;
                    float o0 = xs[co * XST + ll]
                             + fmaxf(acc[nt][h2 * 2 + 0], 0.0f);
                    float o1 = xs[(co + 1) * XST + ll]
                             + fmaxf(acc[nt][h2 * 2 + 1], 0.0f);
                    base[((size_t)(co0h + co) * S + s_cur) * L + l0 + ll]     = o0;
                    base[((size_t)(co0h + co + 1) * S + s_cur) * L + l0 + ll] = o1;
                    __half h0 = __float2half_rn(o0);
                    __half h1 = __float2half_rn(o1);
                    uint32_t hi2 = h2u(h0, h1);
                    uint32_t lo2 = h2u(__float2half_rn(o0 - __half2float(h0)),
                                       __float2half_rn(o1 - __half2float(h1)));
                    const uint32_t aoff =
                        (uint32_t)(((ll + 4) * AST + co0h + co) * 2);
                    sts32(smb + oHi + aoff, hi2);
                    sts32(smb + oLo + aoff, lo2);
                    st_dsmem(rbase + oHi + aoff, hi2);
                    st_dsmem(rbase + oLo + aoff, lo2);
                    if (ll < 4) {
                        *(__half2*)&g_halo[b][tile][0][pcur][0][ll][co0h + co] =
                            __halves2half2(h0, h1);
                        *(__half2*)&g_halo[b][tile][0][pcur][1][ll][co0h + co] =
                            *(__half2*)&lo2;
                    }
                    if (ll >= M - 4) {
                        *(__half2*)&g_halo[b][tile][1][pcur][0][ll - (M - 4)][co0h + co] =
                            __halves2half2(h0, h1);
                        *(__half2*)&g_halo[b][tile][1][pcur][1][ll - (M - 4)][co0h + co] =
                            *(__half2*)&lo2;
                    }
                }
            }
        }

        __syncthreads();                      // all halo/buf stores issued
        if (i <= S - 2 && tid == 0) st_rel(fown, (unsigned)i);
        cluster_sync();                       // DSMEM A[pcur] visible to sibling
    }
}

// ---------------------------------------------------------------------------
// Transpose [P, A, B] -> [P, B, A]
// ---------------------------------------------------------------------------
__global__ void transpose_kernel(const float* __restrict__ in,
                                 float* __restrict__ out, int A, int B)
{
    __shared__ float tile[32][33];
    const size_t p = blockIdx.z;
    const int b0 = blockIdx.x * 32;
    const int a0 = blockIdx.y * 32;
    const int tx = threadIdx.x, ty = threadIdx.y;
    const float* ip = in  + p * (size_t)A * B;
    float*       op = out + p * (size_t)A * B;
#pragma unroll
    for (int i = ty; i < 32; i += 8)
        tile[i][tx] = ip[(size_t)(a0+i)*B + (b0+tx)];
    __syncthreads();
#pragma unroll
    for (int i = ty; i < 32; i += 8)
        op[(size_t)(b0+i)*A + (a0+tx)] = tile[tx][i];
}

// Vertical: [B,C,S=H=128,L=W=256], M=32 (8 tiles). Horizontal: S=256,L=128, M=16.
#define PASSV pass_kernel<128,256,32>
#define PASSH pass_kernel<256,128,16>

static constexpr int SMEM_V = 4*(40*136*2) + KS*64*136*2 + 64*36*4;  // 209408
static constexpr int SMEM_H = 4*(24*136*2) + KS*64*136*2 + 64*20*4;  // 187904

extern "C" void kernel_launch(void* const* d_in, const int* in_sizes, int n_in,
                              void* d_out, int out_size)
{
    const float* x    = (const float*)d_in[0];
    const float* w_ud = (const float*)d_in[1];
    const float* w_du = (const float*)d_in[2];
    const float* w_lr = (const float*)d_in[3];
    const float* w_rl = (const float*)d_in[4];
    float* buf = (float*)d_out;

    float* tbuf = nullptr;
    cudaGetSymbolAddress((void**)&tbuf, g_tmp);
    unsigned* flags = nullptr;
    cudaGetSymbolAddress((void**)&flags, g_flags);

    cudaFuncSetAttribute(PASSV, cudaFuncAttributeMaxDynamicSharedMemorySize, SMEM_V);
    cudaFuncSetAttribute(PASSH, cudaFuncAttributeMaxDynamicSharedMemorySize, SMEM_H);

    cudaMemsetAsync(flags, 0, 4 * BATCH * 8 * 2 * 8 * sizeof(unsigned), 0);
    cudaMemcpyAsync(buf, x, (size_t)NTOT * sizeof(float),
                    cudaMemcpyDeviceToDevice, 0);

    const unsigned PSTRIDE = BATCH * 8 * 2 * 8;

    dim3 g(2, 8, BATCH);   // 128 CTAs = 64 clusters of 2, all resident
    PASSV<<<g, 256, SMEM_V>>>(buf, w_ud, flags + 0*PSTRIDE, 0);
    PASSV<<<g, 256, SMEM_V>>>(buf, w_du, flags + 1*PSTRIDE, 1);

    transpose_kernel<<<dim3(WW/32, HH/32, BATCH*CCH), dim3(32,8)>>>(buf, tbuf, HH, WW);

    PASSH<<<g, 256, SMEM_H>>>(tbuf, w_lr, flags + 2*PSTRIDE, 0);
    PASSH<<<g, 256, SMEM_H>>>(tbuf, w_rl, flags + 3*PSTRIDE, 1);

    transpose_kernel<<<dim3(HH/32, WW/32, BATCH*CCH), dim3(32,8)>>>(tbuf, buf, WW, HH);
}